// round 13
// baseline (speedup 1.0000x reference)
#include <cuda_runtime.h>
#include <cuda_fp16.h>

#define N_USERS 100000
#define N_ITEMS 50000
#define N_NODES 150000
#define N_EDGES 4800000
#define EMBD    64
#define NLAYERS 3
#define BATCH   16384

#define SCAN_BLK   1024
#define SCAN_NBLK  ((N_NODES + SCAN_BLK - 1) / SCAN_BLK)   // 147
#define CNT_PAD    (SCAN_NBLK * SCAN_BLK)

#define TSTRIDE 68   // padded row stride (floats) for smem T tiles
#define WS2     68   // padded row stride (float2) for smem weight hi-pairs

typedef unsigned long long ull;

// Scratch (static __device__, no allocation)
__device__ float    g_E[4][(size_t)N_NODES * EMBD];
__device__ __half   g_Eh[3][(size_t)N_NODES * EMBD];   // fp16 mirror for spmm gathers
__device__ float    g_S[(size_t)N_NODES * EMBD];
__device__ int      g_cnt[CNT_PAD];
__device__ int      g_incl[CNT_PAD];
__device__ int      g_blockSums[SCAN_NBLK];
__device__ int      g_rowstart[N_NODES];
__device__ int      g_cursor[N_NODES];
__device__ int2     g_edge[N_EDGES];   // (col, val*2^112 as int)

// ---------------- f32x2 helpers ----------------
__device__ __forceinline__ ull f2fma(ull a, ull b, ull c) {
    ull d; asm("fma.rn.f32x2 %0, %1, %2, %3;" : "=l"(d) : "l"(a), "l"(b), "l"(c)); return d;
}
__device__ __forceinline__ ull f2add(ull a, ull b) {
    ull d; asm("add.rn.f32x2 %0, %1, %2;" : "=l"(d) : "l"(a), "l"(b)); return d;
}
__device__ __forceinline__ ull dup2(float x) {
    ull d; asm("mov.b64 %0, {%1, %1};" : "=l"(d) : "f"(x)); return d;
}
// fp16x2 -> f32x2 scaled by 2^-112, EXACT for all finite fp16 (ALU ops only,
// no F2F). The 2^112 compensation is folded into vals at scatter time.
__device__ __forceinline__ ull h2f2_raw(unsigned u) {
    unsigned lo = ((u << 13) & 0x0FFFE000u) | ((u << 16) & 0x80000000u);
    unsigned hi = ((u >> 3)  & 0x0FFFE000u) | (u & 0x80000000u);
    ull d; asm("mov.b64 %0, {%1, %2};" : "=l"(d) : "r"(lo), "r"(hi));
    return d;
}

// ---------------- tf32 split + mma helpers ----------------
__device__ __forceinline__ void tf32_split(float x, unsigned& hi, unsigned& lo) {
    unsigned h; asm("cvt.rna.tf32.f32 %0, %1;" : "=r"(h) : "f"(x));
    hi = h;
    lo = __float_as_uint(x - __uint_as_float(h));
}
__device__ __forceinline__ unsigned tf32_hi(float x) {
    unsigned h; asm("cvt.rna.tf32.f32 %0, %1;" : "=r"(h) : "f"(x));
    return h;
}
__device__ __forceinline__ void mma_tf32(float* C,
                                         unsigned a0, unsigned a1, unsigned a2, unsigned a3,
                                         unsigned b0, unsigned b1) {
    asm volatile("mma.sync.aligned.m16n8k8.row.col.f32.tf32.tf32.f32 "
                 "{%0,%1,%2,%3},{%4,%5,%6,%7},{%8,%9},{%0,%1,%2,%3};"
                 : "+f"(C[0]), "+f"(C[1]), "+f"(C[2]), "+f"(C[3])
                 : "r"(a0), "r"(a1), "r"(a2), "r"(a3), "r"(b0), "r"(b1));
}

// ---------------------------------------------------------------------------
// E0 = concat(user_emb, item_emb) (fp32 + fp16 mirror); zero CSR counters.
// ---------------------------------------------------------------------------
__global__ __launch_bounds__(256) void k_concat(const float4* __restrict__ ue,
                                                const float4* __restrict__ ie) {
    int i = blockIdx.x * 256 + threadIdx.x;
    const int nu4 = N_USERS * 16;
    const int nt4 = N_NODES * 16;
    if (i < CNT_PAD) g_cnt[i] = 0;
    if (i >= nt4) return;
    float4 v = (i < nu4) ? __ldg(&ue[i]) : __ldg(&ie[i - nu4]);
    reinterpret_cast<float4*>(g_E[0])[i] = v;
    __half2 h0 = __floats2half2_rn(v.x, v.y);
    __half2 h1 = __floats2half2_rn(v.z, v.w);
    uint2 packed = make_uint2(*reinterpret_cast<unsigned*>(&h0),
                              *reinterpret_cast<unsigned*>(&h1));
    reinterpret_cast<uint2*>(g_Eh[0])[i] = packed;
}

// ---------------- CSR build ----------------
__global__ __launch_bounds__(256) void k_hist(const int* __restrict__ rows, int nedges) {
    int e = blockIdx.x * 256 + threadIdx.x;
    if (e >= nedges) return;
    atomicAdd(&g_cnt[__ldcs(&rows[e])], 1);
}

__global__ __launch_bounds__(SCAN_BLK) void k_scan1() {
    __shared__ int temp[SCAN_BLK];
    int tid = threadIdx.x;
    int gi = blockIdx.x * SCAN_BLK + tid;
    int x = g_cnt[gi];
    temp[tid] = x;
    __syncthreads();
#pragma unroll
    for (int off = 1; off < SCAN_BLK; off <<= 1) {
        int t = (tid >= off) ? temp[tid - off] : 0;
        __syncthreads();
        temp[tid] += t;
        __syncthreads();
    }
    g_incl[gi] = temp[tid];
    if (tid == SCAN_BLK - 1) g_blockSums[blockIdx.x] = temp[tid];
}

// scan3 with the blockSums scan inlined (warp 0 per block; removes a launch)
__global__ __launch_bounds__(256) void k_scan3() {
    __shared__ int soff[SCAN_NBLK];
    int tid = threadIdx.x;
    if (tid < 32) {
        int lane = tid;
        int run = 0;
        for (int base = 0; base < SCAN_NBLK; base += 32) {
            int i = base + lane;
            int x = (i < SCAN_NBLK) ? g_blockSums[i] : 0;
            int incl = x;
#pragma unroll
            for (int off = 1; off < 32; off <<= 1) {
                int t = __shfl_up_sync(0xFFFFFFFFu, incl, off);
                if (lane >= off) incl += t;
            }
            if (i < SCAN_NBLK) soff[i] = run + incl - x;
            run += __shfl_sync(0xFFFFFFFFu, incl, 31);
        }
    }
    __syncthreads();
    int i = blockIdx.x * 256 + tid;
    if (i >= N_NODES) return;
    int b = i / SCAN_BLK;
    int excl = g_incl[i] - g_cnt[i] + soff[b];
    g_rowstart[i] = excl;
    g_cursor[i] = excl;
}

__global__ __launch_bounds__(256) void k_scatter(const int* __restrict__ rows,
                                                 const int* __restrict__ cols,
                                                 const float* __restrict__ vals,
                                                 int nedges) {
    int e = blockIdx.x * 256 + threadIdx.x;
    if (e >= nedges) return;
    int r = __ldcs(&rows[e]);
    int pos = atomicAdd(&g_cursor[r], 1);
    // fold the 2^112 compensation for the raw fp16 gathers into val
    float vscaled = __ldcs(&vals[e]) * 0x1p112f;
    g_edge[pos] = make_int2(__ldcs(&cols[e]), __float_as_int(vscaled));
}

// ---------------------------------------------------------------------------
// CSR SpMM on fp16 mirror: 32 threads per row, lane owns 1 u32 (2 halfs).
// 128B (one line) gathered per edge; conversion is 7 ALU ops per u32, exact.
// ---------------------------------------------------------------------------
__global__ __launch_bounds__(256) void k_spmm_h(int in_idx) {
    int t = blockIdx.x * 256 + threadIdx.x;
    int row = t >> 5;
    int lane = t & 31;
    if (row >= N_NODES) return;
    const unsigned* __restrict__ Eh = reinterpret_cast<const unsigned*>(g_Eh[in_idx]);
    int s = g_rowstart[row];
    int end = s + g_cnt[row];
    ull a0 = 0, a1 = 0;
    int e = s;
    for (; e + 2 <= end; e += 2) {
        int2 e0 = __ldg(&g_edge[e]);
        int2 e1 = __ldg(&g_edge[e + 1]);
        unsigned q0 = __ldg(&Eh[(size_t)e0.x * 32 + lane]);
        unsigned q1 = __ldg(&Eh[(size_t)e1.x * 32 + lane]);
        a0 = f2fma(dup2(__int_as_float(e0.y)), h2f2_raw(q0), a0);
        a1 = f2fma(dup2(__int_as_float(e1.y)), h2f2_raw(q1), a1);
    }
    if (e < end) {
        int2 e0 = __ldg(&g_edge[e]);
        unsigned q0 = __ldg(&Eh[(size_t)e0.x * 32 + lane]);
        a0 = f2fma(dup2(__int_as_float(e0.y)), h2f2_raw(q0), a0);
    }
    *reinterpret_cast<ull*>(g_S + (size_t)row * 64 + lane * 2) = f2add(a0, a1);
}

// ---------------------------------------------------------------------------
// Tensor-core dense layer, 2-term tf32 (round-9 config: 70KB smem, 3 blk/SM).
// ---------------------------------------------------------------------------
__device__ __forceinline__ void pass_global(float C[8][4],
                                            const float* __restrict__ A,
                                            int rowbase,
                                            const float2* __restrict__ sWp,
                                            int grp, int tig) {
#pragma unroll
    for (int k0i = 0; k0i < 8; k0i++) {
        int r0 = min(rowbase + grp, N_NODES - 1);
        int r1 = min(rowbase + grp + 8, N_NODES - 1);
        int c = k0i * 8 + tig;
        unsigned ah[4], al[4];
        tf32_split(A[(size_t)r0 * 64 + c],     ah[0], al[0]);
        tf32_split(A[(size_t)r1 * 64 + c],     ah[1], al[1]);
        tf32_split(A[(size_t)r0 * 64 + c + 4], ah[2], al[2]);
        tf32_split(A[(size_t)r1 * 64 + c + 4], ah[3], al[3]);
        const float2* wrow = sWp + (k0i * 4 + tig) * WS2;
#pragma unroll
        for (int nt = 0; nt < 8; nt++) {
            float2 w = wrow[nt * 8 + grp];
            unsigned b0 = __float_as_uint(w.x), b1 = __float_as_uint(w.y);
            mma_tf32(C[nt], ah[0], ah[1], ah[2], ah[3], b0, b1);
            mma_tf32(C[nt], al[0], al[1], al[2], al[3], b0, b1);
        }
    }
}

__device__ __forceinline__ void pass_smem(float C[8][4],
                                          const float* __restrict__ T,
                                          const float2* __restrict__ sWp,
                                          int grp, int tig) {
#pragma unroll
    for (int k0i = 0; k0i < 8; k0i++) {
        int c = k0i * 8 + tig;
        unsigned ah[4], al[4];
        tf32_split(T[grp * TSTRIDE + c],           ah[0], al[0]);
        tf32_split(T[(grp + 8) * TSTRIDE + c],     ah[1], al[1]);
        tf32_split(T[grp * TSTRIDE + c + 4],       ah[2], al[2]);
        tf32_split(T[(grp + 8) * TSTRIDE + c + 4], ah[3], al[3]);
        const float2* wrow = sWp + (k0i * 4 + tig) * WS2;
#pragma unroll
        for (int nt = 0; nt < 8; nt++) {
            float2 w = wrow[nt * 8 + grp];
            unsigned b0 = __float_as_uint(w.x), b1 = __float_as_uint(w.y);
            mma_tf32(C[nt], ah[0], ah[1], ah[2], ah[3], b0, b1);
            mma_tf32(C[nt], al[0], al[1], al[2], al[3], b0, b1);
        }
    }
}

__global__ __launch_bounds__(256) void k_dense(int in_idx,
                                               const float* __restrict__ W1,
                                               const float* __restrict__ b1,
                                               const float* __restrict__ W2,
                                               const float* __restrict__ b2) {
    extern __shared__ float2 smem_dyn[];
    float2* sW1p = smem_dyn;                 // 32*WS2 f2 = 17.4KB
    float2* sW2p = smem_dyn + 32 * WS2;      // 17.4KB
    float*  sT   = reinterpret_cast<float*>(smem_dyn + 64 * WS2);  // 8*16*68 f

    const float* E = g_E[in_idx];
    float* Eout = g_E[in_idx + 1];
    __half* Eouth = (in_idx + 1 < 3) ? g_Eh[in_idx + 1] : (__half*)0;

    int tid = threadIdx.x;
    // Pack weight hi-pairs: p = (k1/8)*4 + k1%4 for k1%8 < 4.
    for (int i = tid; i < 2048; i += 256) {
        int p = i >> 6, col = i & 63;
        int k1 = ((p >> 2) << 3) + (p & 3);
        sW1p[p * WS2 + col] = make_float2(
            __uint_as_float(tf32_hi(W1[k1 * 64 + col])),
            __uint_as_float(tf32_hi(W1[(k1 + 4) * 64 + col])));
        sW2p[p * WS2 + col] = make_float2(
            __uint_as_float(tf32_hi(W2[k1 * 64 + col])),
            __uint_as_float(tf32_hi(W2[(k1 + 4) * 64 + col])));
    }
    __syncthreads();

    int w = tid >> 5, lane = tid & 31;
    int grp = lane >> 2, tig = lane & 3;
    int rowbase = blockIdx.x * 128 + w * 16;
    float* myT = sT + w * (16 * TSTRIDE);

    float C[8][4];
#pragma unroll
    for (int nt = 0; nt < 8; nt++) {
        int col = nt * 8 + tig * 2;
        float v0 = __ldg(&b2[col]), v1 = __ldg(&b2[col + 1]);
        C[nt][0] = v0; C[nt][1] = v1; C[nt][2] = v0; C[nt][3] = v1;
    }

    // Pass 1: C = S @ W2 + b2  (= neighbor)
    pass_global(C, g_S, rowbase, sW2p, grp, tig);

    // T = neighbor * E (elementwise) -> padded smem
    {
        int cr0 = min(rowbase + grp, N_NODES - 1);
        int cr1 = min(rowbase + grp + 8, N_NODES - 1);
#pragma unroll
        for (int nt = 0; nt < 8; nt++) {
            int col = nt * 8 + tig * 2;
            float2 e0 = *reinterpret_cast<const float2*>(E + (size_t)cr0 * 64 + col);
            float2 e1 = *reinterpret_cast<const float2*>(E + (size_t)cr1 * 64 + col);
            *reinterpret_cast<float2*>(myT + grp * TSTRIDE + col) =
                make_float2(C[nt][0] * e0.x, C[nt][1] * e0.y);
            *reinterpret_cast<float2*>(myT + (grp + 8) * TSTRIDE + col) =
                make_float2(C[nt][2] * e1.x, C[nt][3] * e1.y);
        }
    }
    __syncwarp();

    // Pass 2: C += T @ W2
    pass_smem(C, myT, sW2p, grp, tig);

    // Pass 3: C += E @ W1
    pass_global(C, E, rowbase, sW1p, grp, tig);

    // out = LReLU(C + b1 + b2); fp32 + fp16 mirror
    {
        int r0 = rowbase + grp;
        int r1 = rowbase + grp + 8;
#pragma unroll
        for (int nt = 0; nt < 8; nt++) {
            int col = nt * 8 + tig * 2;
            float bb0 = __ldg(&b1[col]) + __ldg(&b2[col]);
            float bb1 = __ldg(&b1[col + 1]) + __ldg(&b2[col + 1]);
            if (r0 < N_NODES) {
                float o0 = C[nt][0] + bb0;
                float o1 = C[nt][1] + bb1;
                o0 = o0 > 0.f ? o0 : 0.2f * o0;
                o1 = o1 > 0.f ? o1 : 0.2f * o1;
                *reinterpret_cast<float2*>(Eout + (size_t)r0 * 64 + col) = make_float2(o0, o1);
                if (Eouth) {
                    __half2 h = __floats2half2_rn(o0, o1);
                    *reinterpret_cast<__half2*>(Eouth + (size_t)r0 * 64 + col) = h;
                }
            }
            if (r1 < N_NODES) {
                float o2 = C[nt][2] + bb0;
                float o3 = C[nt][3] + bb1;
                o2 = o2 > 0.f ? o2 : 0.2f * o2;
                o3 = o3 > 0.f ? o3 : 0.2f * o3;
                *reinterpret_cast<float2*>(Eout + (size_t)r1 * 64 + col) = make_float2(o2, o3);
                if (Eouth) {
                    __half2 h = __floats2half2_rn(o2, o3);
                    *reinterpret_cast<__half2*>(Eouth + (size_t)r1 * 64 + col) = h;
                }
            }
        }
    }
}

// ---------------------------------------------------------------------------
__global__ __launch_bounds__(256) void k_gather(const int* __restrict__ users,
                                                const int* __restrict__ pos,
                                                const int* __restrict__ neg,
                                                float4* __restrict__ out) {
    int gid = blockIdx.x * 256 + threadIdx.x;
    const int total = 3 * BATCH * 64;
    if (gid >= total) return;
    int c4 = gid & 63;
    int row = gid >> 6;
    int seg = row / BATCH;
    int b = row - seg * BATCH;
    int node;
    if (seg == 0)      node = __ldg(&users[b]);
    else if (seg == 1) node = N_USERS + __ldg(&pos[b]);
    else               node = N_USERS + __ldg(&neg[b]);
    int layer = c4 >> 4, w4 = c4 & 15;
    float4 v = __ldg(reinterpret_cast<const float4*>(g_E[layer]) + (size_t)node * 16 + w4);
    out[gid] = v;
}

// ---------------------------------------------------------------------------
extern "C" void kernel_launch(void* const* d_in, const int* in_sizes, int n_in,
                              void* d_out, int out_size) {
    const int*    users = (const int*)d_in[0];
    const int*    pos   = (const int*)d_in[1];
    const int*    neg   = (const int*)d_in[2];
    const int*    rows  = (const int*)d_in[3];
    const int*    cols  = (const int*)d_in[4];
    const float*  vals  = (const float*)d_in[5];
    const float4* ue    = (const float4*)d_in[6];
    const float4* ie    = (const float4*)d_in[7];
    const float*  W1s   = (const float*)d_in[8];
    const float*  b1s   = (const float*)d_in[9];
    const float*  W2s   = (const float*)d_in[10];
    const float*  b2s   = (const float*)d_in[11];
    int nedges = in_sizes[3];

    const int DSMEM = 2 * 32 * WS2 * 8 + 8 * 16 * TSTRIDE * 4;  // 69632
    static int configured = 0;
    if (!configured) {
        cudaFuncSetAttribute(k_dense, cudaFuncAttributeMaxDynamicSharedMemorySize, DSMEM);
        configured = 1;
    }

    const int n4blocks = (N_NODES * 16 + 255) / 256;
    const int eblocks = (nedges + 255) / 256;

    k_concat<<<n4blocks, 256>>>(ue, ie);

    k_hist<<<eblocks, 256>>>(rows, nedges);
    k_scan1<<<SCAN_NBLK, SCAN_BLK>>>();
    k_scan3<<<(N_NODES + 255) / 256, 256>>>();
    k_scatter<<<eblocks, 256>>>(rows, cols, vals, nedges);

    const int spmm_blocks = (N_NODES * 32 + 255) / 256;
    const int dense_blocks = (N_NODES + 127) / 128;
    for (int l = 0; l < NLAYERS; l++) {
        k_spmm_h<<<spmm_blocks, 256>>>(l);
        k_dense<<<dense_blocks, 256, DSMEM>>>(l, W1s + l * 4096, b1s + l * 64,
                                              W2s + l * 4096, b2s + l * 64);
    }

    k_gather<<<(3 * BATCH * 64 + 255) / 256, 256>>>(users, pos, neg, (float4*)d_out);
}

// round 14
// speedup vs baseline: 1.0712x; 1.0712x over previous
#include <cuda_runtime.h>

#define N_USERS 100000
#define N_ITEMS 50000
#define N_NODES 150000
#define N_EDGES 4800000
#define EMBD    64
#define NLAYERS 3
#define BATCH   16384

#define SCAN_BLK   1024
#define SCAN_NBLK  ((N_NODES + SCAN_BLK - 1) / SCAN_BLK)   // 147
#define CNT_PAD    (SCAN_NBLK * SCAN_BLK)

#define TSTRIDE 68   // padded row stride (floats) for smem T tiles
#define WS2     68   // padded row stride (float2) for smem weight hi-pairs

typedef unsigned long long ull;

// Scratch (static __device__, no allocation)
__device__ float g_E[4][(size_t)N_NODES * EMBD];
__device__ float g_S[(size_t)N_NODES * EMBD];
__device__ int   g_cnt[CNT_PAD];
__device__ int   g_incl[CNT_PAD];
__device__ int   g_blockSums[SCAN_NBLK];
__device__ int   g_rowstart[N_NODES];
__device__ int   g_cursor[N_NODES];
__device__ int2  g_edge[N_EDGES];   // (col, val-as-int)

// ---------------- f32x2 helpers (spmm) ----------------
__device__ __forceinline__ ull f2fma(ull a, ull b, ull c) {
    ull d; asm("fma.rn.f32x2 %0, %1, %2, %3;" : "=l"(d) : "l"(a), "l"(b), "l"(c)); return d;
}
__device__ __forceinline__ ull f2add(ull a, ull b) {
    ull d; asm("add.rn.f32x2 %0, %1, %2;" : "=l"(d) : "l"(a), "l"(b)); return d;
}
__device__ __forceinline__ ull dup2(float x) {
    ull d; asm("mov.b64 %0, {%1, %1};" : "=l"(d) : "f"(x)); return d;
}

// ---------------- tf32 split + mma helpers ----------------
__device__ __forceinline__ void tf32_split(float x, unsigned& hi, unsigned& lo) {
    unsigned h; asm("cvt.rna.tf32.f32 %0, %1;" : "=r"(h) : "f"(x));
    hi = h;
    lo = __float_as_uint(x - __uint_as_float(h));
}
__device__ __forceinline__ unsigned tf32_hi(float x) {
    unsigned h; asm("cvt.rna.tf32.f32 %0, %1;" : "=r"(h) : "f"(x));
    return h;
}
__device__ __forceinline__ void mma_tf32(float* C,
                                         unsigned a0, unsigned a1, unsigned a2, unsigned a3,
                                         unsigned b0, unsigned b1) {
    asm volatile("mma.sync.aligned.m16n8k8.row.col.f32.tf32.tf32.f32 "
                 "{%0,%1,%2,%3},{%4,%5,%6,%7},{%8,%9},{%0,%1,%2,%3};"
                 : "+f"(C[0]), "+f"(C[1]), "+f"(C[2]), "+f"(C[3])
                 : "r"(a0), "r"(a1), "r"(a2), "r"(a3), "r"(b0), "r"(b1));
}

// ---------------------------------------------------------------------------
// E0 = concat(user_emb, item_emb); zero CSR counters.
// ---------------------------------------------------------------------------
__global__ __launch_bounds__(256) void k_concat(const float4* __restrict__ ue,
                                                const float4* __restrict__ ie) {
    int i = blockIdx.x * 256 + threadIdx.x;
    const int nu4 = N_USERS * 16;
    const int nt4 = N_NODES * 16;
    if (i < CNT_PAD) g_cnt[i] = 0;
    if (i >= nt4) return;
    float4 v = (i < nu4) ? __ldg(&ue[i]) : __ldg(&ie[i - nu4]);
    reinterpret_cast<float4*>(g_E[0])[i] = v;
}

// ---------------- CSR build ----------------
__global__ __launch_bounds__(256) void k_hist(const int* __restrict__ rows, int nedges) {
    int e = blockIdx.x * 256 + threadIdx.x;
    if (e >= nedges) return;
    atomicAdd(&g_cnt[__ldcs(&rows[e])], 1);
}

__global__ __launch_bounds__(SCAN_BLK) void k_scan1() {
    __shared__ int temp[SCAN_BLK];
    int tid = threadIdx.x;
    int gi = blockIdx.x * SCAN_BLK + tid;
    int x = g_cnt[gi];
    temp[tid] = x;
    __syncthreads();
#pragma unroll
    for (int off = 1; off < SCAN_BLK; off <<= 1) {
        int t = (tid >= off) ? temp[tid - off] : 0;
        __syncthreads();
        temp[tid] += t;
        __syncthreads();
    }
    g_incl[gi] = temp[tid];
    if (tid == SCAN_BLK - 1) g_blockSums[blockIdx.x] = temp[tid];
}

// scan3 with the blockSums scan inlined (warp 0 per block; removes a launch)
__global__ __launch_bounds__(256) void k_scan3() {
    __shared__ int soff[SCAN_NBLK];
    int tid = threadIdx.x;
    if (tid < 32) {
        int lane = tid;
        int run = 0;
        for (int base = 0; base < SCAN_NBLK; base += 32) {
            int i = base + lane;
            int x = (i < SCAN_NBLK) ? g_blockSums[i] : 0;
            int incl = x;
#pragma unroll
            for (int off = 1; off < 32; off <<= 1) {
                int t = __shfl_up_sync(0xFFFFFFFFu, incl, off);
                if (lane >= off) incl += t;
            }
            if (i < SCAN_NBLK) soff[i] = run + incl - x;
            run += __shfl_sync(0xFFFFFFFFu, incl, 31);
        }
    }
    __syncthreads();
    int i = blockIdx.x * 256 + tid;
    if (i >= N_NODES) return;
    int b = i / SCAN_BLK;
    int excl = g_incl[i] - g_cnt[i] + soff[b];
    g_rowstart[i] = excl;
    g_cursor[i] = excl;
}

__global__ __launch_bounds__(256) void k_scatter(const int* __restrict__ rows,
                                                 const int* __restrict__ cols,
                                                 const float* __restrict__ vals,
                                                 int nedges) {
    int e = blockIdx.x * 256 + threadIdx.x;
    if (e >= nedges) return;
    int r = __ldcs(&rows[e]);
    int pos = atomicAdd(&g_cursor[r], 1);
    g_edge[pos] = make_int2(__ldcs(&cols[e]), __float_as_int(__ldcs(&vals[e])));
}

// ---------------------------------------------------------------------------
// CSR SpMM: 16 threads per row, lane owns one float4 chunk (LDG.128 gathers).
// Edge loads streamed (__ldcs) to keep E + S resident in L2. 8-edge unroll.
// ---------------------------------------------------------------------------
__global__ __launch_bounds__(256) void k_spmm_csr(int in_idx) {
    int t = blockIdx.x * 256 + threadIdx.x;
    int row = t >> 4;
    int c = t & 15;
    if (row >= N_NODES) return;
    const float4* __restrict__ E4 = reinterpret_cast<const float4*>(g_E[in_idx]);
    int s = g_rowstart[row];
    int end = s + g_cnt[row];
    ull a0x = 0, a0y = 0, a1x = 0, a1y = 0;
    int e = s;
    for (; e + 8 <= end; e += 8) {
        int2 e0 = __ldcs(&g_edge[e + 0]), e1 = __ldcs(&g_edge[e + 1]);
        int2 e2 = __ldcs(&g_edge[e + 2]), e3 = __ldcs(&g_edge[e + 3]);
        int2 e4 = __ldcs(&g_edge[e + 4]), e5 = __ldcs(&g_edge[e + 5]);
        int2 e6 = __ldcs(&g_edge[e + 6]), e7 = __ldcs(&g_edge[e + 7]);
        float4 x0 = __ldg(&E4[(size_t)e0.x * 16 + c]);
        float4 x1 = __ldg(&E4[(size_t)e1.x * 16 + c]);
        float4 x2 = __ldg(&E4[(size_t)e2.x * 16 + c]);
        float4 x3 = __ldg(&E4[(size_t)e3.x * 16 + c]);
        float4 x4 = __ldg(&E4[(size_t)e4.x * 16 + c]);
        float4 x5 = __ldg(&E4[(size_t)e5.x * 16 + c]);
        float4 x6 = __ldg(&E4[(size_t)e6.x * 16 + c]);
        float4 x7 = __ldg(&E4[(size_t)e7.x * 16 + c]);
        ull v0 = dup2(__int_as_float(e0.y)), v1 = dup2(__int_as_float(e1.y));
        ull v2 = dup2(__int_as_float(e2.y)), v3 = dup2(__int_as_float(e3.y));
        ull v4 = dup2(__int_as_float(e4.y)), v5 = dup2(__int_as_float(e5.y));
        ull v6 = dup2(__int_as_float(e6.y)), v7 = dup2(__int_as_float(e7.y));
        ulonglong2 p0 = *reinterpret_cast<ulonglong2*>(&x0);
        ulonglong2 p1 = *reinterpret_cast<ulonglong2*>(&x1);
        ulonglong2 p2 = *reinterpret_cast<ulonglong2*>(&x2);
        ulonglong2 p3 = *reinterpret_cast<ulonglong2*>(&x3);
        ulonglong2 p4 = *reinterpret_cast<ulonglong2*>(&x4);
        ulonglong2 p5 = *reinterpret_cast<ulonglong2*>(&x5);
        ulonglong2 p6 = *reinterpret_cast<ulonglong2*>(&x6);
        ulonglong2 p7 = *reinterpret_cast<ulonglong2*>(&x7);
        a0x = f2fma(v0, p0.x, a0x); a0y = f2fma(v0, p0.y, a0y);
        a1x = f2fma(v1, p1.x, a1x); a1y = f2fma(v1, p1.y, a1y);
        a0x = f2fma(v2, p2.x, a0x); a0y = f2fma(v2, p2.y, a0y);
        a1x = f2fma(v3, p3.x, a1x); a1y = f2fma(v3, p3.y, a1y);
        a0x = f2fma(v4, p4.x, a0x); a0y = f2fma(v4, p4.y, a0y);
        a1x = f2fma(v5, p5.x, a1x); a1y = f2fma(v5, p5.y, a1y);
        a0x = f2fma(v6, p6.x, a0x); a0y = f2fma(v6, p6.y, a0y);
        a1x = f2fma(v7, p7.x, a1x); a1y = f2fma(v7, p7.y, a1y);
    }
    for (; e < end; e++) {
        int2 ed = __ldcs(&g_edge[e]);
        float4 x = __ldg(&E4[(size_t)ed.x * 16 + c]);
        ull v = dup2(__int_as_float(ed.y));
        ulonglong2 p = *reinterpret_cast<ulonglong2*>(&x);
        a0x = f2fma(v, p.x, a0x);
        a0y = f2fma(v, p.y, a0y);
    }
    ulonglong2 r;
    r.x = f2add(a0x, a1x);
    r.y = f2add(a0y, a1y);
    reinterpret_cast<ulonglong2*>(g_S)[(size_t)row * 16 + c] = r;
}

// ---------------------------------------------------------------------------
// Tensor-core dense layer, 2-term tf32 (R9 config: 70KB smem, 3 blk/SM).
// ---------------------------------------------------------------------------
__device__ __forceinline__ void pass_global(float C[8][4],
                                            const float* __restrict__ A,
                                            int rowbase,
                                            const float2* __restrict__ sWp,
                                            int grp, int tig) {
#pragma unroll
    for (int k0i = 0; k0i < 8; k0i++) {
        int r0 = min(rowbase + grp, N_NODES - 1);
        int r1 = min(rowbase + grp + 8, N_NODES - 1);
        int c = k0i * 8 + tig;
        unsigned ah[4], al[4];
        tf32_split(A[(size_t)r0 * 64 + c],     ah[0], al[0]);
        tf32_split(A[(size_t)r1 * 64 + c],     ah[1], al[1]);
        tf32_split(A[(size_t)r0 * 64 + c + 4], ah[2], al[2]);
        tf32_split(A[(size_t)r1 * 64 + c + 4], ah[3], al[3]);
        const float2* wrow = sWp + (k0i * 4 + tig) * WS2;
#pragma unroll
        for (int nt = 0; nt < 8; nt++) {
            float2 w = wrow[nt * 8 + grp];
            unsigned b0 = __float_as_uint(w.x), b1 = __float_as_uint(w.y);
            mma_tf32(C[nt], ah[0], ah[1], ah[2], ah[3], b0, b1);
            mma_tf32(C[nt], al[0], al[1], al[2], al[3], b0, b1);
        }
    }
}

__device__ __forceinline__ void pass_smem(float C[8][4],
                                          const float* __restrict__ T,
                                          const float2* __restrict__ sWp,
                                          int grp, int tig) {
#pragma unroll
    for (int k0i = 0; k0i < 8; k0i++) {
        int c = k0i * 8 + tig;
        unsigned ah[4], al[4];
        tf32_split(T[grp * TSTRIDE + c],           ah[0], al[0]);
        tf32_split(T[(grp + 8) * TSTRIDE + c],     ah[1], al[1]);
        tf32_split(T[grp * TSTRIDE + c + 4],       ah[2], al[2]);
        tf32_split(T[(grp + 8) * TSTRIDE + c + 4], ah[3], al[3]);
        const float2* wrow = sWp + (k0i * 4 + tig) * WS2;
#pragma unroll
        for (int nt = 0; nt < 8; nt++) {
            float2 w = wrow[nt * 8 + grp];
            unsigned b0 = __float_as_uint(w.x), b1 = __float_as_uint(w.y);
            mma_tf32(C[nt], ah[0], ah[1], ah[2], ah[3], b0, b1);
            mma_tf32(C[nt], al[0], al[1], al[2], al[3], b0, b1);
        }
    }
}

__global__ __launch_bounds__(256) void k_dense(int in_idx,
                                               const float* __restrict__ W1,
                                               const float* __restrict__ b1,
                                               const float* __restrict__ W2,
                                               const float* __restrict__ b2) {
    extern __shared__ float2 smem_dyn[];
    float2* sW1p = smem_dyn;                 // 32*WS2 f2 = 17.4KB
    float2* sW2p = smem_dyn + 32 * WS2;      // 17.4KB
    float*  sT   = reinterpret_cast<float*>(smem_dyn + 64 * WS2);  // 8*16*68 f

    const float* E = g_E[in_idx];
    float* Eout = g_E[in_idx + 1];

    int tid = threadIdx.x;
    // Pack weight hi-pairs: p = (k1/8)*4 + k1%4 for k1%8 < 4.
    for (int i = tid; i < 2048; i += 256) {
        int p = i >> 6, col = i & 63;
        int k1 = ((p >> 2) << 3) + (p & 3);
        sW1p[p * WS2 + col] = make_float2(
            __uint_as_float(tf32_hi(W1[k1 * 64 + col])),
            __uint_as_float(tf32_hi(W1[(k1 + 4) * 64 + col])));
        sW2p[p * WS2 + col] = make_float2(
            __uint_as_float(tf32_hi(W2[k1 * 64 + col])),
            __uint_as_float(tf32_hi(W2[(k1 + 4) * 64 + col])));
    }
    __syncthreads();

    int w = tid >> 5, lane = tid & 31;
    int grp = lane >> 2, tig = lane & 3;
    int rowbase = blockIdx.x * 128 + w * 16;
    float* myT = sT + w * (16 * TSTRIDE);

    float C[8][4];
#pragma unroll
    for (int nt = 0; nt < 8; nt++) {
        int col = nt * 8 + tig * 2;
        float v0 = __ldg(&b2[col]), v1 = __ldg(&b2[col + 1]);
        C[nt][0] = v0; C[nt][1] = v1; C[nt][2] = v0; C[nt][3] = v1;
    }

    // Pass 1: C = S @ W2 + b2  (= neighbor)
    pass_global(C, g_S, rowbase, sW2p, grp, tig);

    // T = neighbor * E (elementwise) -> padded smem
    {
        int cr0 = min(rowbase + grp, N_NODES - 1);
        int cr1 = min(rowbase + grp + 8, N_NODES - 1);
#pragma unroll
        for (int nt = 0; nt < 8; nt++) {
            int col = nt * 8 + tig * 2;
            float2 e0 = *reinterpret_cast<const float2*>(E + (size_t)cr0 * 64 + col);
            float2 e1 = *reinterpret_cast<const float2*>(E + (size_t)cr1 * 64 + col);
            *reinterpret_cast<float2*>(myT + grp * TSTRIDE + col) =
                make_float2(C[nt][0] * e0.x, C[nt][1] * e0.y);
            *reinterpret_cast<float2*>(myT + (grp + 8) * TSTRIDE + col) =
                make_float2(C[nt][2] * e1.x, C[nt][3] * e1.y);
        }
    }
    __syncwarp();

    // Pass 2: C += T @ W2
    pass_smem(C, myT, sW2p, grp, tig);

    // Pass 3: C += E @ W1
    pass_global(C, E, rowbase, sW1p, grp, tig);

    // out = LReLU(C + b1 + b2)
    {
        int r0 = rowbase + grp;
        int r1 = rowbase + grp + 8;
#pragma unroll
        for (int nt = 0; nt < 8; nt++) {
            int col = nt * 8 + tig * 2;
            float bb0 = __ldg(&b1[col]) + __ldg(&b2[col]);
            float bb1 = __ldg(&b1[col + 1]) + __ldg(&b2[col + 1]);
            if (r0 < N_NODES) {
                float o0 = C[nt][0] + bb0;
                float o1 = C[nt][1] + bb1;
                o0 = o0 > 0.f ? o0 : 0.2f * o0;
                o1 = o1 > 0.f ? o1 : 0.2f * o1;
                *reinterpret_cast<float2*>(Eout + (size_t)r0 * 64 + col) = make_float2(o0, o1);
            }
            if (r1 < N_NODES) {
                float o2 = C[nt][2] + bb0;
                float o3 = C[nt][3] + bb1;
                o2 = o2 > 0.f ? o2 : 0.2f * o2;
                o3 = o3 > 0.f ? o3 : 0.2f * o3;
                *reinterpret_cast<float2*>(Eout + (size_t)r1 * 64 + col) = make_float2(o2, o3);
            }
        }
    }
}

// ---------------------------------------------------------------------------
__global__ __launch_bounds__(256) void k_gather(const int* __restrict__ users,
                                                const int* __restrict__ pos,
                                                const int* __restrict__ neg,
                                                float4* __restrict__ out) {
    int gid = blockIdx.x * 256 + threadIdx.x;
    const int total = 3 * BATCH * 64;
    if (gid >= total) return;
    int c4 = gid & 63;
    int row = gid >> 6;
    int seg = row / BATCH;
    int b = row - seg * BATCH;
    int node;
    if (seg == 0)      node = __ldg(&users[b]);
    else if (seg == 1) node = N_USERS + __ldg(&pos[b]);
    else               node = N_USERS + __ldg(&neg[b]);
    int layer = c4 >> 4, w4 = c4 & 15;
    float4 v = __ldg(reinterpret_cast<const float4*>(g_E[layer]) + (size_t)node * 16 + w4);
    out[gid] = v;
}

// ---------------------------------------------------------------------------
extern "C" void kernel_launch(void* const* d_in, const int* in_sizes, int n_in,
                              void* d_out, int out_size) {
    const int*    users = (const int*)d_in[0];
    const int*    pos   = (const int*)d_in[1];
    const int*    neg   = (const int*)d_in[2];
    const int*    rows  = (const int*)d_in[3];
    const int*    cols  = (const int*)d_in[4];
    const float*  vals  = (const float*)d_in[5];
    const float4* ue    = (const float4*)d_in[6];
    const float4* ie    = (const float4*)d_in[7];
    const float*  W1s   = (const float*)d_in[8];
    const float*  b1s   = (const float*)d_in[9];
    const float*  W2s   = (const float*)d_in[10];
    const float*  b2s   = (const float*)d_in[11];
    int nedges = in_sizes[3];

    const int DSMEM = 2 * 32 * WS2 * 8 + 8 * 16 * TSTRIDE * 4;  // 69632
    static int configured = 0;
    if (!configured) {
        cudaFuncSetAttribute(k_dense, cudaFuncAttributeMaxDynamicSharedMemorySize, DSMEM);
        configured = 1;
    }

    const int n4blocks = (N_NODES * 16 + 255) / 256;
    const int eblocks = (nedges + 255) / 256;

    k_concat<<<n4blocks, 256>>>(ue, ie);

    k_hist<<<eblocks, 256>>>(rows, nedges);
    k_scan1<<<SCAN_NBLK, SCAN_BLK>>>();
    k_scan3<<<(N_NODES + 255) / 256, 256>>>();
    k_scatter<<<eblocks, 256>>>(rows, cols, vals, nedges);

    const int spmm_blocks = (N_NODES * 16 + 255) / 256;
    const int dense_blocks = (N_NODES + 127) / 128;
    for (int l = 0; l < NLAYERS; l++) {
        k_spmm_csr<<<spmm_blocks, 256>>>(l);
        k_dense<<<dense_blocks, 256, DSMEM>>>(l, W1s + l * 4096, b1s + l * 64,
                                              W2s + l * 4096, b2s + l * 64);
    }

    k_gather<<<(3 * BATCH * 64 + 255) / 256, 256>>>(users, pos, neg, (float4*)d_out);
}

// round 15
// speedup vs baseline: 1.1988x; 1.1191x over previous
#include <cuda_runtime.h>

#define N_USERS 100000
#define N_ITEMS 50000
#define N_NODES 150000
#define N_EDGES 4800000
#define EMBD    64
#define NLAYERS 3
#define BATCH   16384

#define SCAN_BLK   1024
#define SCAN_NBLK  ((N_NODES + SCAN_BLK - 1) / SCAN_BLK)   // 147
#define CNT_PAD    (SCAN_NBLK * SCAN_BLK)

#define TSTRIDE 68   // padded row stride (floats) for smem T tiles
#define WS2     68   // padded row stride (float2) for smem weight hi-pairs

typedef unsigned long long ull;

// Scratch (static __device__, no allocation)
__device__ float g_E[4][(size_t)N_NODES * EMBD];
__device__ float g_S[(size_t)N_NODES * EMBD];
__device__ int   g_cnt[CNT_PAD];
__device__ int   g_incl[CNT_PAD];
__device__ int   g_blockSums[SCAN_NBLK];
__device__ int   g_rowstart[N_NODES];
__device__ int   g_cursor[N_NODES];
__device__ int2  g_edge[N_EDGES];   // (col, val-as-int)

// ---------------- f32x2 helpers (spmm) ----------------
__device__ __forceinline__ ull f2fma(ull a, ull b, ull c) {
    ull d; asm("fma.rn.f32x2 %0, %1, %2, %3;" : "=l"(d) : "l"(a), "l"(b), "l"(c)); return d;
}
__device__ __forceinline__ ull f2add(ull a, ull b) {
    ull d; asm("add.rn.f32x2 %0, %1, %2;" : "=l"(d) : "l"(a), "l"(b)); return d;
}
__device__ __forceinline__ ull dup2(float x) {
    ull d; asm("mov.b64 %0, {%1, %1};" : "=l"(d) : "f"(x)); return d;
}

// ---------------- tf32 split + mma helpers ----------------
__device__ __forceinline__ void tf32_split(float x, unsigned& hi, unsigned& lo) {
    unsigned h; asm("cvt.rna.tf32.f32 %0, %1;" : "=r"(h) : "f"(x));
    hi = h;
    lo = __float_as_uint(x - __uint_as_float(h));
}
__device__ __forceinline__ unsigned tf32_hi(float x) {
    unsigned h; asm("cvt.rna.tf32.f32 %0, %1;" : "=r"(h) : "f"(x));
    return h;
}
__device__ __forceinline__ void mma_tf32(float* C,
                                         unsigned a0, unsigned a1, unsigned a2, unsigned a3,
                                         unsigned b0, unsigned b1) {
    asm volatile("mma.sync.aligned.m16n8k8.row.col.f32.tf32.tf32.f32 "
                 "{%0,%1,%2,%3},{%4,%5,%6,%7},{%8,%9},{%0,%1,%2,%3};"
                 : "+f"(C[0]), "+f"(C[1]), "+f"(C[2]), "+f"(C[3])
                 : "r"(a0), "r"(a1), "r"(a2), "r"(a3), "r"(b0), "r"(b1));
}

// ---------------------------------------------------------------------------
// E0 = concat(user_emb, item_emb); zero CSR counters.
// ---------------------------------------------------------------------------
__global__ __launch_bounds__(256) void k_concat(const float4* __restrict__ ue,
                                                const float4* __restrict__ ie) {
    int i = blockIdx.x * 256 + threadIdx.x;
    const int nu4 = N_USERS * 16;
    const int nt4 = N_NODES * 16;
    if (i < CNT_PAD) g_cnt[i] = 0;
    if (i >= nt4) return;
    float4 v = (i < nu4) ? __ldg(&ue[i]) : __ldg(&ie[i - nu4]);
    reinterpret_cast<float4*>(g_E[0])[i] = v;
}

// ---------------- CSR build ----------------
__global__ __launch_bounds__(256) void k_hist(const int* __restrict__ rows, int nedges) {
    int e = blockIdx.x * 256 + threadIdx.x;
    if (e >= nedges) return;
    atomicAdd(&g_cnt[__ldcs(&rows[e])], 1);
}

__global__ __launch_bounds__(SCAN_BLK) void k_scan1() {
    __shared__ int temp[SCAN_BLK];
    int tid = threadIdx.x;
    int gi = blockIdx.x * SCAN_BLK + tid;
    int x = g_cnt[gi];
    temp[tid] = x;
    __syncthreads();
#pragma unroll
    for (int off = 1; off < SCAN_BLK; off <<= 1) {
        int t = (tid >= off) ? temp[tid - off] : 0;
        __syncthreads();
        temp[tid] += t;
        __syncthreads();
    }
    g_incl[gi] = temp[tid];
    if (tid == SCAN_BLK - 1) g_blockSums[blockIdx.x] = temp[tid];
}

// scan3 with the blockSums scan inlined (warp 0 per block; removes a launch)
__global__ __launch_bounds__(256) void k_scan3() {
    __shared__ int soff[SCAN_NBLK];
    int tid = threadIdx.x;
    if (tid < 32) {
        int lane = tid;
        int run = 0;
        for (int base = 0; base < SCAN_NBLK; base += 32) {
            int i = base + lane;
            int x = (i < SCAN_NBLK) ? g_blockSums[i] : 0;
            int incl = x;
#pragma unroll
            for (int off = 1; off < 32; off <<= 1) {
                int t = __shfl_up_sync(0xFFFFFFFFu, incl, off);
                if (lane >= off) incl += t;
            }
            if (i < SCAN_NBLK) soff[i] = run + incl - x;
            run += __shfl_sync(0xFFFFFFFFu, incl, 31);
        }
    }
    __syncthreads();
    int i = blockIdx.x * 256 + tid;
    if (i >= N_NODES) return;
    int b = i / SCAN_BLK;
    int excl = g_incl[i] - g_cnt[i] + soff[b];
    g_rowstart[i] = excl;
    g_cursor[i] = excl;
}

__global__ __launch_bounds__(256) void k_scatter(const int* __restrict__ rows,
                                                 const int* __restrict__ cols,
                                                 const float* __restrict__ vals,
                                                 int nedges) {
    int e = blockIdx.x * 256 + threadIdx.x;
    if (e >= nedges) return;
    int r = __ldcs(&rows[e]);
    int pos = atomicAdd(&g_cursor[r], 1);
    g_edge[pos] = make_int2(__ldcs(&cols[e]), __float_as_int(__ldcs(&vals[e])));
}

// ---------------------------------------------------------------------------
// CSR SpMM: 16 threads per row, lane owns one float4 chunk (LDG.128 gathers).
// R9 loop verbatim: __ldg edge loads (L2-resident across layers), 4-edge unroll.
// ---------------------------------------------------------------------------
__global__ __launch_bounds__(256) void k_spmm_csr(int in_idx) {
    int t = blockIdx.x * 256 + threadIdx.x;
    int row = t >> 4;
    int c = t & 15;
    if (row >= N_NODES) return;
    const float4* __restrict__ E4 = reinterpret_cast<const float4*>(g_E[in_idx]);
    int s = g_rowstart[row];
    int end = s + g_cnt[row];
    ull a0x = 0, a0y = 0, a1x = 0, a1y = 0;
    int e = s;
    for (; e + 4 <= end; e += 4) {
        int2 e0 = __ldg(&g_edge[e + 0]), e1 = __ldg(&g_edge[e + 1]);
        int2 e2 = __ldg(&g_edge[e + 2]), e3 = __ldg(&g_edge[e + 3]);
        float4 x0 = __ldg(&E4[(size_t)e0.x * 16 + c]);
        float4 x1 = __ldg(&E4[(size_t)e1.x * 16 + c]);
        float4 x2 = __ldg(&E4[(size_t)e2.x * 16 + c]);
        float4 x3 = __ldg(&E4[(size_t)e3.x * 16 + c]);
        ull v0 = dup2(__int_as_float(e0.y)), v1 = dup2(__int_as_float(e1.y));
        ull v2 = dup2(__int_as_float(e2.y)), v3 = dup2(__int_as_float(e3.y));
        ulonglong2 p0 = *reinterpret_cast<ulonglong2*>(&x0);
        ulonglong2 p1 = *reinterpret_cast<ulonglong2*>(&x1);
        ulonglong2 p2 = *reinterpret_cast<ulonglong2*>(&x2);
        ulonglong2 p3 = *reinterpret_cast<ulonglong2*>(&x3);
        a0x = f2fma(v0, p0.x, a0x); a0y = f2fma(v0, p0.y, a0y);
        a1x = f2fma(v1, p1.x, a1x); a1y = f2fma(v1, p1.y, a1y);
        a0x = f2fma(v2, p2.x, a0x); a0y = f2fma(v2, p2.y, a0y);
        a1x = f2fma(v3, p3.x, a1x); a1y = f2fma(v3, p3.y, a1y);
    }
    for (; e < end; e++) {
        int2 ed = __ldg(&g_edge[e]);
        float4 x = __ldg(&E4[(size_t)ed.x * 16 + c]);
        ull v = dup2(__int_as_float(ed.y));
        ulonglong2 p = *reinterpret_cast<ulonglong2*>(&x);
        a0x = f2fma(v, p.x, a0x);
        a0y = f2fma(v, p.y, a0y);
    }
    ulonglong2 r;
    r.x = f2add(a0x, a1x);
    r.y = f2add(a0y, a1y);
    reinterpret_cast<ulonglong2*>(g_S)[(size_t)row * 16 + c] = r;
}

// ---------------------------------------------------------------------------
// Tensor-core dense layer, 2-term tf32 (R9 config: 70KB smem, 3 blk/SM).
// ---------------------------------------------------------------------------
__device__ __forceinline__ void pass_global(float C[8][4],
                                            const float* __restrict__ A,
                                            int rowbase,
                                            const float2* __restrict__ sWp,
                                            int grp, int tig) {
#pragma unroll
    for (int k0i = 0; k0i < 8; k0i++) {
        int r0 = min(rowbase + grp, N_NODES - 1);
        int r1 = min(rowbase + grp + 8, N_NODES - 1);
        int c = k0i * 8 + tig;
        unsigned ah[4], al[4];
        tf32_split(A[(size_t)r0 * 64 + c],     ah[0], al[0]);
        tf32_split(A[(size_t)r1 * 64 + c],     ah[1], al[1]);
        tf32_split(A[(size_t)r0 * 64 + c + 4], ah[2], al[2]);
        tf32_split(A[(size_t)r1 * 64 + c + 4], ah[3], al[3]);
        const float2* wrow = sWp + (k0i * 4 + tig) * WS2;
#pragma unroll
        for (int nt = 0; nt < 8; nt++) {
            float2 w = wrow[nt * 8 + grp];
            unsigned b0 = __float_as_uint(w.x), b1 = __float_as_uint(w.y);
            mma_tf32(C[nt], ah[0], ah[1], ah[2], ah[3], b0, b1);
            mma_tf32(C[nt], al[0], al[1], al[2], al[3], b0, b1);
        }
    }
}

__device__ __forceinline__ void pass_smem(float C[8][4],
                                          const float* __restrict__ T,
                                          const float2* __restrict__ sWp,
                                          int grp, int tig) {
#pragma unroll
    for (int k0i = 0; k0i < 8; k0i++) {
        int c = k0i * 8 + tig;
        unsigned ah[4], al[4];
        tf32_split(T[grp * TSTRIDE + c],           ah[0], al[0]);
        tf32_split(T[(grp + 8) * TSTRIDE + c],     ah[1], al[1]);
        tf32_split(T[grp * TSTRIDE + c + 4],       ah[2], al[2]);
        tf32_split(T[(grp + 8) * TSTRIDE + c + 4], ah[3], al[3]);
        const float2* wrow = sWp + (k0i * 4 + tig) * WS2;
#pragma unroll
        for (int nt = 0; nt < 8; nt++) {
            float2 w = wrow[nt * 8 + grp];
            unsigned b0 = __float_as_uint(w.x), b1 = __float_as_uint(w.y);
            mma_tf32(C[nt], ah[0], ah[1], ah[2], ah[3], b0, b1);
            mma_tf32(C[nt], al[0], al[1], al[2], al[3], b0, b1);
        }
    }
}

__global__ __launch_bounds__(256) void k_dense(int in_idx,
                                               const float* __restrict__ W1,
                                               const float* __restrict__ b1,
                                               const float* __restrict__ W2,
                                               const float* __restrict__ b2) {
    extern __shared__ float2 smem_dyn[];
    float2* sW1p = smem_dyn;                 // 32*WS2 f2 = 17.4KB
    float2* sW2p = smem_dyn + 32 * WS2;      // 17.4KB
    float*  sT   = reinterpret_cast<float*>(smem_dyn + 64 * WS2);  // 8*16*68 f

    const float* E = g_E[in_idx];
    float* Eout = g_E[in_idx + 1];

    int tid = threadIdx.x;
    // Pack weight hi-pairs: p = (k1/8)*4 + k1%4 for k1%8 < 4.
    for (int i = tid; i < 2048; i += 256) {
        int p = i >> 6, col = i & 63;
        int k1 = ((p >> 2) << 3) + (p & 3);
        sW1p[p * WS2 + col] = make_float2(
            __uint_as_float(tf32_hi(W1[k1 * 64 + col])),
            __uint_as_float(tf32_hi(W1[(k1 + 4) * 64 + col])));
        sW2p[p * WS2 + col] = make_float2(
            __uint_as_float(tf32_hi(W2[k1 * 64 + col])),
            __uint_as_float(tf32_hi(W2[(k1 + 4) * 64 + col])));
    }
    __syncthreads();

    int w = tid >> 5, lane = tid & 31;
    int grp = lane >> 2, tig = lane & 3;
    int rowbase = blockIdx.x * 128 + w * 16;
    float* myT = sT + w * (16 * TSTRIDE);

    float C[8][4];
#pragma unroll
    for (int nt = 0; nt < 8; nt++) {
        int col = nt * 8 + tig * 2;
        float v0 = __ldg(&b2[col]), v1 = __ldg(&b2[col + 1]);
        C[nt][0] = v0; C[nt][1] = v1; C[nt][2] = v0; C[nt][3] = v1;
    }

    // Pass 1: C = S @ W2 + b2  (= neighbor)
    pass_global(C, g_S, rowbase, sW2p, grp, tig);

    // T = neighbor * E (elementwise) -> padded smem
    {
        int cr0 = min(rowbase + grp, N_NODES - 1);
        int cr1 = min(rowbase + grp + 8, N_NODES - 1);
#pragma unroll
        for (int nt = 0; nt < 8; nt++) {
            int col = nt * 8 + tig * 2;
            float2 e0 = *reinterpret_cast<const float2*>(E + (size_t)cr0 * 64 + col);
            float2 e1 = *reinterpret_cast<const float2*>(E + (size_t)cr1 * 64 + col);
            *reinterpret_cast<float2*>(myT + grp * TSTRIDE + col) =
                make_float2(C[nt][0] * e0.x, C[nt][1] * e0.y);
            *reinterpret_cast<float2*>(myT + (grp + 8) * TSTRIDE + col) =
                make_float2(C[nt][2] * e1.x, C[nt][3] * e1.y);
        }
    }
    __syncwarp();

    // Pass 2: C += T @ W2
    pass_smem(C, myT, sW2p, grp, tig);

    // Pass 3: C += E @ W1
    pass_global(C, E, rowbase, sW1p, grp, tig);

    // out = LReLU(C + b1 + b2)
    {
        int r0 = rowbase + grp;
        int r1 = rowbase + grp + 8;
#pragma unroll
        for (int nt = 0; nt < 8; nt++) {
            int col = nt * 8 + tig * 2;
            float bb0 = __ldg(&b1[col]) + __ldg(&b2[col]);
            float bb1 = __ldg(&b1[col + 1]) + __ldg(&b2[col + 1]);
            if (r0 < N_NODES) {
                float o0 = C[nt][0] + bb0;
                float o1 = C[nt][1] + bb1;
                o0 = o0 > 0.f ? o0 : 0.2f * o0;
                o1 = o1 > 0.f ? o1 : 0.2f * o1;
                *reinterpret_cast<float2*>(Eout + (size_t)r0 * 64 + col) = make_float2(o0, o1);
            }
            if (r1 < N_NODES) {
                float o2 = C[nt][2] + bb0;
                float o3 = C[nt][3] + bb1;
                o2 = o2 > 0.f ? o2 : 0.2f * o2;
                o3 = o3 > 0.f ? o3 : 0.2f * o3;
                *reinterpret_cast<float2*>(Eout + (size_t)r1 * 64 + col) = make_float2(o2, o3);
            }
        }
    }
}

// ---------------------------------------------------------------------------
__global__ __launch_bounds__(256) void k_gather(const int* __restrict__ users,
                                                const int* __restrict__ pos,
                                                const int* __restrict__ neg,
                                                float4* __restrict__ out) {
    int gid = blockIdx.x * 256 + threadIdx.x;
    const int total = 3 * BATCH * 64;
    if (gid >= total) return;
    int c4 = gid & 63;
    int row = gid >> 6;
    int seg = row / BATCH;
    int b = row - seg * BATCH;
    int node;
    if (seg == 0)      node = __ldg(&users[b]);
    else if (seg == 1) node = N_USERS + __ldg(&pos[b]);
    else               node = N_USERS + __ldg(&neg[b]);
    int layer = c4 >> 4, w4 = c4 & 15;
    float4 v = __ldg(reinterpret_cast<const float4*>(g_E[layer]) + (size_t)node * 16 + w4);
    out[gid] = v;
}

// ---------------------------------------------------------------------------
extern "C" void kernel_launch(void* const* d_in, const int* in_sizes, int n_in,
                              void* d_out, int out_size) {
    const int*    users = (const int*)d_in[0];
    const int*    pos   = (const int*)d_in[1];
    const int*    neg   = (const int*)d_in[2];
    const int*    rows  = (const int*)d_in[3];
    const int*    cols  = (const int*)d_in[4];
    const float*  vals  = (const float*)d_in[5];
    const float4* ue    = (const float4*)d_in[6];
    const float4* ie    = (const float4*)d_in[7];
    const float*  W1s   = (const float*)d_in[8];
    const float*  b1s   = (const float*)d_in[9];
    const float*  W2s   = (const float*)d_in[10];
    const float*  b2s   = (const float*)d_in[11];
    int nedges = in_sizes[3];

    const int DSMEM = 2 * 32 * WS2 * 8 + 8 * 16 * TSTRIDE * 4;  // 69632
    static int configured = 0;
    if (!configured) {
        cudaFuncSetAttribute(k_dense, cudaFuncAttributeMaxDynamicSharedMemorySize, DSMEM);
        configured = 1;
    }

    const int n4blocks = (N_NODES * 16 + 255) / 256;
    const int eblocks = (nedges + 255) / 256;

    k_concat<<<n4blocks, 256>>>(ue, ie);

    k_hist<<<eblocks, 256>>>(rows, nedges);
    k_scan1<<<SCAN_NBLK, SCAN_BLK>>>();
    k_scan3<<<(N_NODES + 255) / 256, 256>>>();
    k_scatter<<<eblocks, 256>>>(rows, cols, vals, nedges);

    const int spmm_blocks = (N_NODES * 16 + 255) / 256;
    const int dense_blocks = (N_NODES + 127) / 128;
    for (int l = 0; l < NLAYERS; l++) {
        k_spmm_csr<<<spmm_blocks, 256>>>(l);
        k_dense<<<dense_blocks, 256, DSMEM>>>(l, W1s + l * 4096, b1s + l * 64,
                                              W2s + l * 4096, b2s + l * 64);
    }

    k_gather<<<(3 * BATCH * 64 + 255) / 256, 256>>>(users, pos, neg, (float4*)d_out);
}